// round 3
// baseline (speedup 1.0000x reference)
#include <cuda_runtime.h>
#include <cuda_bf16.h>
#include <math.h>
#include <cstdint>

// Problem constants (fixed by the dataset)
constexpr int Bn = 4096, Tn = 32, Xn = 256, Hn = 256, Zn = 256, Gn = 128, Yn = 2;
constexpr int BT = Bn * Tn; // 131072

#define DI __device__ __forceinline__

DI uint32_t smem_u32(const void* p) {
    uint32_t a;
    asm("{ .reg .u64 t; cvta.to.shared.u64 t, %1; cvt.u32.u64 %0, t; }" : "=r"(a) : "l"(p));
    return a;
}
DI float sigf(float x) { return 1.0f / (1.0f + expf(-x)); }

DI uint32_t packbf(float a, float b) {
    __nv_bfloat162 t = __floats2bfloat162_rn(a, b);
    return reinterpret_cast<uint32_t&>(t);
}
DI uint32_t packlo(float a, float b) {
    float ra = a - __bfloat162float(__float2bfloat16(a));
    float rb = b - __bfloat162float(__float2bfloat16(b));
    return packbf(ra, rb);
}

DI void ldm_x4(uint32_t r[4], uint32_t addr) {
    asm volatile("ldmatrix.sync.aligned.m8n8.x4.shared.b16 {%0,%1,%2,%3}, [%4];"
                 : "=r"(r[0]), "=r"(r[1]), "=r"(r[2]), "=r"(r[3]) : "r"(addr));
}
DI void mma_bf16(float d[4], const uint32_t a[4], const uint32_t b[2]) {
    asm volatile(
        "mma.sync.aligned.m16n8k16.row.col.f32.bf16.bf16.f32 "
        "{%0,%1,%2,%3}, {%4,%5,%6,%7}, {%8,%9}, {%0,%1,%2,%3};"
        : "+f"(d[0]), "+f"(d[1]), "+f"(d[2]), "+f"(d[3])
        : "r"(a[0]), "r"(a[1]), "r"(a[2]), "r"(a[3]), "r"(b[0]), "r"(b[1]));
}

// ============================ static device scratch ============================
__device__ float g_AX [131072 * 1280];   // x-projections: [r,u,h,zp,zq]
__device__ float g_CAT[131072 * 768];    // packed [x | h | z]
__device__ float g_H  [33 * 4096 * 256];
__device__ float g_Z  [33 * 4096 * 256];
__device__ float g_R  [4096 * 256];
__device__ float g_U  [4096 * 256];
__device__ float g_HZP[4096 * 256];
__device__ float g_HZQ[4096 * 256];
__device__ float g_HD [4096 * 1024];
__device__ float g_G  [131072 * 128];
// prepacked weights: bf16 [N][3K] = [hi | hi | lo], transposed, K-major
constexpr size_t O1 = 0;                 // [1280][768]
constexpr size_t O2 = O1 + 1280 * 768;   // [512][1536]
constexpr size_t O3 = O2 + 512 * 1536;   // [256][1536]
constexpr size_t O4 = O3 + 256 * 1536;   // [512][768]
constexpr size_t O5 = O4 + 512 * 768;    // [1024][768]
constexpr size_t O6 = O5 + 1024 * 768;   // [128][2304]
constexpr size_t WTOT = O6 + 128 * 2304;
__device__ __nv_bfloat16 g_Wp[WTOT];

// ============================ A loaders ============================
struct APlain {
    const float* p; int ld;
    DI float4 ld4(int r, int k, int) const { return *(const float4*)(p + (size_t)r * ld + k); }
};
struct ACat2 { // [h_prev | z_prev]
    const float* a; const float* b;
    DI float4 ld4(int r, int k, int) const {
        const float* q = (k < 256) ? (a + (size_t)r * 256 + k) : (b + (size_t)r * 256 + (k - 256));
        return *(const float4*)q;
    }
};
struct ACat2Mul { // [r*h_prev | z_prev]
    const float* rg; const float* h; const float* z;
    DI float4 ld4(int r, int k, int) const {
        if (k < 256) {
            float4 rv = *(const float4*)(rg + (size_t)r * 256 + k);
            float4 hv = *(const float4*)(h  + (size_t)r * 256 + k);
            return make_float4(rv.x * hv.x, rv.y * hv.y, rv.z * hv.z, rv.w * hv.w);
        }
        return *(const float4*)(z + (size_t)r * 256 + (k - 256));
    }
};
struct ASel { // heads GEMM: nseg 0,1 -> HZP ; 2,3 -> HZQ
    const float* a0; const float* a1;
    DI float4 ld4(int r, int k, int nseg) const {
        const float* q = (nseg < 2 ? a0 : a1) + (size_t)r * 256 + k;
        return *(const float4*)q;
    }
};

// ============================ Epilogues ============================
struct EP_AX {
    float* AX; const float* bias[5]; const float* yph; const float* WzqY;
    DI void operator()(int row, int col, float acc) const {
        int seg = col >> 8, c = col & 255;
        float v = acc + bias[seg][c];
        if (seg == 4)
            v += yph[(size_t)row * 2] * WzqY[c] + yph[(size_t)row * 2 + 1] * WzqY[256 + c];
        AX[(size_t)row * 1280 + col] = v;
    }
};
struct EP_RU {
    const float* AX; float* R; float* U; int t;
    DI void operator()(int b, int col, float acc) const {
        size_t bt = (size_t)b * Tn + t;
        if (col < 256) R[b * 256 + col]       = sigf(acc + AX[bt * 1280 + col]);
        else           U[b * 256 + col - 256] = sigf(acc + AX[bt * 1280 + col]);
    }
};
struct EP_H {
    const float* AX; const float* U; const float* hp; float* Hout; float* CAT; int t;
    DI void operator()(int b, int c, float acc) const {
        size_t bt = (size_t)b * Tn + t;
        float ht = tanhf(acc + AX[bt * 1280 + 512 + c]);
        float u  = U[b * 256 + c];
        float h0 = hp[b * 256 + c];
        float h  = (1.0f - u) * h0 + u * ht;
        Hout[b * 256 + c] = h;
        CAT[bt * 768 + 256 + c] = h;
    }
};
struct EP_ZPQ {
    const float* AX; float* HZP; float* HZQ; int t;
    DI void operator()(int b, int col, float acc) const {
        size_t bt = (size_t)b * Tn + t;
        if (col < 256) HZP[b * 256 + col]       = tanhf(acc + AX[bt * 1280 + 768 + col]);
        else           HZQ[b * 256 + col - 256] = tanhf(acc + AX[bt * 1280 + 1024 + (col - 256)]);
    }
};
struct EP_HEADS {
    float* HD; const float* bias[4];
    DI void operator()(int b, int col, float acc) const {
        int seg = col >> 8, c = col & 255;
        HD[(size_t)b * 1024 + col] = acc + bias[seg][c];
    }
};
struct EP_G {
    float* G; const float* bg;
    DI void operator()(int row, int col, float acc) const {
        G[(size_t)row * 128 + col] = tanhf(acc + bg[col]);
    }
};

// ============================ bf16 split mma.sync GEMM ============================
// CTA tile 128x64, BK=32 bf16 (one split-term K-chunk). K' = 3K (hi*hi + lo*hi + hi*lo).
// 8 warps in 2(m) x 4(n); warp tile 64x16 -> 4 m-frags(16) x 2 n-frags(8).
// SMEM rows padded to 80B (5*16B) => conflict-free ldmatrix. Double buffered.
constexpr int A_TILE = 128 * 80;  // 10240 B
constexpr int B_TILE = 64 * 80;   // 5120 B
constexpr int BUF    = A_TILE + B_TILE;

template <class AL, class EP>
__global__ __launch_bounds__(256)
void tgemm(AL al, EP ep, const __nv_bfloat16* __restrict__ Bp, int K) {
    __shared__ __align__(16) uint8_t smem[2][BUF];

    const int tid  = threadIdx.x;
    const int lane = tid & 31;
    const int warp = tid >> 5;
    const int m0 = blockIdx.y * 128;
    const int n0 = blockIdx.x * 64;
    const int nseg  = n0 >> 8;
    const int warpM = (warp >> 2) * 64;
    const int warpN = (warp & 3) * 16;
    const int K3 = 3 * K;

    // fill coords
    const int ar = tid >> 1;            // A row 0..127
    const int ak = (tid & 1) << 4;      // A k offset 0 / 16
    const int brr = tid >> 2;           // B row 0..63
    const int bcc = tid & 3;            // B 16B chunk 0..3

    float acc[4][2][4];
#pragma unroll
    for (int i = 0; i < 4; i++)
#pragma unroll
        for (int j = 0; j < 2; j++)
#pragma unroll
            for (int q = 0; q < 4; q++) acc[i][j][q] = 0.0f;

    const int kchunks = K >> 5;
    const int nch = kchunks * 3;

    float4 va[4];
    uint4  vb;
    int term = 0, kb = 0; // coords of chunk being prefetched

    auto loadN = [&](int) {
#pragma unroll
        for (int q = 0; q < 4; q++)
            va[q] = al.ld4(m0 + ar, kb + ak + q * 4, nseg);
    };
    auto loadB = [&](int ch) {
        vb = *(const uint4*)(Bp + (size_t)(n0 + brr) * K3 + ch * 32 + bcc * 8);
    };
    auto store = [&](int buf, bool lo) {
        uint4 w0, w1;
        if (!lo) {
            w0 = make_uint4(packbf(va[0].x, va[0].y), packbf(va[0].z, va[0].w),
                            packbf(va[1].x, va[1].y), packbf(va[1].z, va[1].w));
            w1 = make_uint4(packbf(va[2].x, va[2].y), packbf(va[2].z, va[2].w),
                            packbf(va[3].x, va[3].y), packbf(va[3].z, va[3].w));
        } else {
            w0 = make_uint4(packlo(va[0].x, va[0].y), packlo(va[0].z, va[0].w),
                            packlo(va[1].x, va[1].y), packlo(va[1].z, va[1].w));
            w1 = make_uint4(packlo(va[2].x, va[2].y), packlo(va[2].z, va[2].w),
                            packlo(va[3].x, va[3].y), packlo(va[3].z, va[3].w));
        }
        uint8_t* Ab = &smem[buf][0] + ar * 80 + (ak >> 3) * 16;
        *(uint4*)(Ab)      = w0;
        *(uint4*)(Ab + 16) = w1;
        *(uint4*)(&smem[buf][A_TILE] + brr * 80 + bcc * 16) = vb;
    };
    auto mmastep = [&](int buf) {
        const uint32_t Ab = smem_u32(&smem[buf][0]);
        const uint32_t Bb = Ab + A_TILE;
#pragma unroll
        for (int ks = 0; ks < 2; ks++) {
            uint32_t afr[4][4];
#pragma unroll
            for (int mf = 0; mf < 4; mf++)
                ldm_x4(afr[mf], Ab + (warpM + mf * 16 + (lane & 15)) * 80
                                   + ((ks << 1) + (lane >> 4)) * 16);
            uint32_t bfr[4];
            ldm_x4(bfr, Bb + (warpN + (lane & 7) + ((lane >> 4) & 1) * 8) * 80
                           + ((ks << 1) + ((lane >> 3) & 1)) * 16);
#pragma unroll
            for (int mf = 0; mf < 4; mf++)
#pragma unroll
                for (int nf = 0; nf < 2; nf++)
                    mma_bf16(acc[mf][nf], afr[mf], bfr + nf * 2);
        }
    };

    // prologue: chunk 0
    loadN(0); loadB(0);
    store(0, false);
    __syncthreads();

    for (int i = 0; i < nch; i++) {
        bool nlo = false;
        if (i + 1 < nch) {
            kb += 32;
            if (kb == K) { kb = 0; term++; }
            nlo = (term == 1);
            loadN(i + 1);
            loadB(i + 1);
        }
        mmastep(i & 1);
        if (i + 1 < nch) store((i + 1) & 1, nlo);
        __syncthreads();
    }

    // register-direct fused epilogue (mma.m16n8k16 C fragment mapping)
#pragma unroll
    for (int mf = 0; mf < 4; mf++)
#pragma unroll
        for (int nf = 0; nf < 2; nf++)
#pragma unroll
            for (int j = 0; j < 4; j++) {
                int m = m0 + warpM + mf * 16 + (lane >> 2) + ((j >> 1) << 3);
                int n = n0 + warpN + nf * 8 + ((lane & 3) << 1) + (j & 1);
                ep(m, n, acc[mf][nf][j]);
            }
}

// ============================ weight prep ============================
__global__ void prep_w(const float* __restrict__ src, int src_ld, int src_row0,
                       __nv_bfloat16* __restrict__ dst, int dst_row0, int Kfull,
                       int kslice0, int Krows, int Ncols) {
    int idx = blockIdx.x * 256 + threadIdx.x;
    if (idx >= Krows * Ncols) return;
    int k = idx / Ncols, n = idx % Ncols;
    float v = src[(size_t)(src_row0 + k) * src_ld + n];
    __nv_bfloat16 hi = __float2bfloat16(v);
    __nv_bfloat16 lo = __float2bfloat16(v - __bfloat162float(hi));
    size_t base = (size_t)(dst_row0 + n) * (3 * Kfull) + kslice0 + k;
    dst[base]             = hi;
    dst[base + Kfull]     = hi;
    dst[base + 2 * Kfull] = lo;
}

// ============================ small kernels ============================
__global__ void init_copy(const float* __restrict__ x, const float* __restrict__ h0,
                          const float* __restrict__ z0, float* __restrict__ CAT,
                          float* __restrict__ Hb, float* __restrict__ Zb) {
    size_t idx = (size_t)blockIdx.x * blockDim.x + threadIdx.x;
    size_t r = idx >> 8, k = idx & 255;
    CAT[r * 768 + k] = x[idx];
    if (idx < (size_t)Bn * Hn) { Hb[idx] = h0[idx]; Zb[idx] = z0[idx]; }
}

__global__ void step_latent(const float* __restrict__ HD, const float* __restrict__ eps_t,
                            float* __restrict__ Zout, float* __restrict__ CAT,
                            float* __restrict__ outKL, int t) {
    int b = blockIdx.x, c = threadIdx.x;
    size_t hb = (size_t)b * 1024;
    float mup = HD[hb + c];
    float lp  = HD[hb + 256 + c];
    float muq = HD[hb + 512 + c];
    float lq  = HD[hb + 768 + c];
    float z = muq + expf(0.5f * lq) * eps_t[b * 256 + c];
    Zout[b * 256 + c] = z;
    size_t bt = (size_t)b * Tn + t;
    CAT[bt * 768 + 512 + c] = z;
    float d = muq - mup;
    float kl = 0.5f * (lp - lq) + (expf(lq) + d * d) / (2.0f * expf(lp)) - 0.5f;

    __shared__ float red[8];
    for (int o = 16; o; o >>= 1) kl += __shfl_down_sync(0xffffffffu, kl, o);
    if ((threadIdx.x & 31) == 0) red[threadIdx.x >> 5] = kl;
    __syncthreads();
    if (threadIdx.x == 0) {
        float s = 0.0f;
#pragma unroll
        for (int i = 0; i < 8; i++) s += red[i];
        outKL[bt] = s;
    }
}

__global__ void yhead(const float* __restrict__ G, const float* __restrict__ Wy,
                      const float* __restrict__ by, float* __restrict__ outY) {
    int r = blockIdx.x * 8 + (threadIdx.x >> 5);
    int lane = threadIdx.x & 31;
    float s0 = 0.0f, s1 = 0.0f;
    const float* g = G + (size_t)r * 128;
    for (int k = lane; k < 128; k += 32) {
        float gv = g[k];
        s0 += gv * Wy[k * 2];
        s1 += gv * Wy[k * 2 + 1];
    }
    for (int o = 16; o; o >>= 1) {
        s0 += __shfl_down_sync(0xffffffffu, s0, o);
        s1 += __shfl_down_sync(0xffffffffu, s1, o);
    }
    if (lane == 0) {
        float l0 = s0 + by[0], l1 = s1 + by[1];
        float m = fmaxf(l0, l1);
        float e0 = expf(l0 - m), e1 = expf(l1 - m);
        float inv = 1.0f / (e0 + e1);
        outY[(size_t)r * 2]     = e0 * inv;
        outY[(size_t)r * 2 + 1] = e1 * inv;
    }
}

__global__ void gatherGT(const float* __restrict__ G, const int* __restrict__ Tph,
                         float* __restrict__ outGT) {
    int b = blockIdx.x;
    int t = Tph[b] - 1;
    outGT[(size_t)b * Gn + threadIdx.x] = G[((size_t)b * Tn + t) * Gn + threadIdx.x];
}

// ============================ launch ============================
extern "C" void kernel_launch(void* const* d_in, const int* in_sizes, int n_in,
                              void* d_out, int out_size) {
    const float* x   = (const float*)d_in[0];
    const float* yph = (const float*)d_in[1];
    const int*   Tph = (const int*)  d_in[2];
    const float* h0  = (const float*)d_in[3];
    const float* z0  = (const float*)d_in[4];
    const float* eps = (const float*)d_in[5];
    const float* Wr  = (const float*)d_in[6];  const float* br  = (const float*)d_in[7];
    const float* Wu  = (const float*)d_in[8];  const float* bu  = (const float*)d_in[9];
    const float* Wh  = (const float*)d_in[10]; const float* bh  = (const float*)d_in[11];
    const float* Wzp = (const float*)d_in[12]; const float* bzp = (const float*)d_in[13];
    const float* Wpm = (const float*)d_in[14]; const float* bpm = (const float*)d_in[15];
    const float* Wps = (const float*)d_in[16]; const float* bps = (const float*)d_in[17];
    const float* Wzq = (const float*)d_in[18]; const float* bzq = (const float*)d_in[19];
    const float* Wqm = (const float*)d_in[20]; const float* bqm = (const float*)d_in[21];
    const float* Wqs = (const float*)d_in[22]; const float* bqs = (const float*)d_in[23];
    const float* Wg  = (const float*)d_in[24]; const float* bg  = (const float*)d_in[25];
    const float* Wy  = (const float*)d_in[26]; const float* by  = (const float*)d_in[27];

    float *AX, *CAT, *Hb, *Zb, *Rb, *Ub, *HZP, *HZQ, *HD, *Gb;
    __nv_bfloat16* Wp;
    {
        void* p;
        cudaGetSymbolAddress(&p, g_AX);  AX  = (float*)p;
        cudaGetSymbolAddress(&p, g_CAT); CAT = (float*)p;
        cudaGetSymbolAddress(&p, g_H);   Hb  = (float*)p;
        cudaGetSymbolAddress(&p, g_Z);   Zb  = (float*)p;
        cudaGetSymbolAddress(&p, g_R);   Rb  = (float*)p;
        cudaGetSymbolAddress(&p, g_U);   Ub  = (float*)p;
        cudaGetSymbolAddress(&p, g_HZP); HZP = (float*)p;
        cudaGetSymbolAddress(&p, g_HZQ); HZQ = (float*)p;
        cudaGetSymbolAddress(&p, g_HD);  HD  = (float*)p;
        cudaGetSymbolAddress(&p, g_G);   Gb  = (float*)p;
        cudaGetSymbolAddress(&p, g_Wp);  Wp  = (__nv_bfloat16*)p;
    }

    float* out   = (float*)d_out;
    float* outY  = out;
    float* outKL = out + (size_t)BT * Yn;
    float* outGT = out + (size_t)BT * Yn + BT;

    // ---- weight prep: transpose + bf16 hi/lo split into [N][3K] ----
    auto prep = [&](const float* src, int src_ld, int src_row0, size_t dst_off,
                    int dst_row0, int Kfull, int kslice0, int Krows, int Ncols) {
        int tot = Krows * Ncols;
        prep_w<<<(tot + 255) / 256, 256>>>(src, src_ld, src_row0, Wp + dst_off,
                                           dst_row0, Kfull, kslice0, Krows, Ncols);
    };
    // W1: x-parts of r,u,h,zp,zq -> [1280][3*256]
    prep(Wr,  256, 0, O1,    0, 256, 0, 256, 256);
    prep(Wu,  256, 0, O1,  256, 256, 0, 256, 256);
    prep(Wh,  256, 0, O1,  512, 256, 0, 256, 256);
    prep(Wzp, 256, 0, O1,  768, 256, 0, 256, 256);
    prep(Wzq, 256, 0, O1, 1024, 256, 0, 256, 256);
    // W2: gates h|z parts -> [512][3*512]
    prep(Wr,  256, 256, O2,   0, 512, 0, 512, 256);
    prep(Wu,  256, 256, O2, 256, 512, 0, 512, 256);
    // W3: cand h|z part -> [256][3*512]
    prep(Wh,  256, 256, O3,   0, 512, 0, 512, 256);
    // W4: latent h-parts -> [512][3*256]
    prep(Wzp, 256, 256, O4,   0, 256, 0, 256, 256);
    prep(Wzq, 256, 256, O4, 256, 256, 0, 256, 256);
    // W5: heads -> [1024][3*256]
    prep(Wpm, 256, 0, O5,   0, 256, 0, 256, 256);
    prep(Wps, 256, 0, O5, 256, 256, 0, 256, 256);
    prep(Wqm, 256, 0, O5, 512, 256, 0, 256, 256);
    prep(Wqs, 256, 0, O5, 768, 256, 0, 256, 256);
    // W6: Wg [768][128] -> [128][3*768]
    prep(Wg,  128, 0, O6,   0, 768, 0, 768, 128);

    // init: pack x into CAT, seed h0/z0
    init_copy<<<BT, 256>>>(x, h0, z0, CAT, Hb, Zb);

    // phase 1: all x-projections  [131072,256] @ [256,1280]
    {
        APlain al{x, Xn};
        EP_AX ep;
        ep.AX = AX;
        ep.bias[0] = br; ep.bias[1] = bu; ep.bias[2] = bh; ep.bias[3] = bzp; ep.bias[4] = bzq;
        ep.yph = yph; ep.WzqY = Wzq + 512 * 256;
        tgemm<<<dim3(1280 / 64, BT / 128), 256>>>(al, ep, Wp + O1, 256);
    }

    // phase 2: sequential scan
    for (int t = 0; t < Tn; t++) {
        const float* hp = Hb + (size_t)t * Bn * Hn;
        const float* zp = Zb + (size_t)t * Bn * Zn;
        float* hn = Hb + (size_t)(t + 1) * Bn * Hn;
        float* zn = Zb + (size_t)(t + 1) * Bn * Zn;

        { // gates r,u
            ACat2 al{hp, zp};
            EP_RU ep{AX, Rb, Ub, t};
            tgemm<<<dim3(512 / 64, Bn / 128), 256>>>(al, ep, Wp + O2, 512);
        }
        { // candidate + GRU update
            ACat2Mul al{Rb, hp, zp};
            EP_H ep{AX, Ub, hp, hn, CAT, t};
            tgemm<<<dim3(256 / 64, Bn / 128), 256>>>(al, ep, Wp + O3, 512);
        }
        { // latent hiddens
            APlain al{hn, Hn};
            EP_ZPQ ep{AX, HZP, HZQ, t};
            tgemm<<<dim3(512 / 64, Bn / 128), 256>>>(al, ep, Wp + O4, 256);
        }
        { // heads
            ASel al{HZP, HZQ};
            EP_HEADS ep;
            ep.HD = HD;
            ep.bias[0] = bpm; ep.bias[1] = bps; ep.bias[2] = bqm; ep.bias[3] = bqs;
            tgemm<<<dim3(1024 / 64, Bn / 128), 256>>>(al, ep, Wp + O5, 256);
        }
        step_latent<<<Bn, 256>>>(HD, eps + (size_t)t * Bn * Zn, zn, CAT, outKL, t);
    }

    // phase 3: g = tanh(CAT @ Wg + bg)
    {
        APlain al{CAT, 768};
        EP_G ep{Gb, bg};
        tgemm<<<dim3(Gn / 64, BT / 128), 256>>>(al, ep, Wp + O6, 768);
    }
    yhead<<<BT / 8, 256>>>(Gb, Wy, by, outY);
    gatherGT<<<Bn, Gn>>>(Gb, Tph, outGT);
}

// round 4
// speedup vs baseline: 1.2933x; 1.2933x over previous
#include <cuda_runtime.h>
#include <cuda_bf16.h>
#include <math.h>
#include <cstdint>

// Problem constants (fixed by the dataset)
constexpr int Bn = 4096, Tn = 32, Xn = 256, Hn = 256, Zn = 256, Gn = 128, Yn = 2;
constexpr int BT = Bn * Tn; // 131072

#define DI __device__ __forceinline__

DI uint32_t smem_u32(const void* p) {
    uint32_t a;
    asm("{ .reg .u64 t; cvta.to.shared.u64 t, %1; cvt.u32.u64 %0, t; }" : "=r"(a) : "l"(p));
    return a;
}
DI float sigf(float x) { return 1.0f / (1.0f + expf(-x)); }

DI void ldm_x4(uint32_t r[4], uint32_t addr) {
    asm volatile("ldmatrix.sync.aligned.m8n8.x4.shared.b16 {%0,%1,%2,%3}, [%4];"
                 : "=r"(r[0]), "=r"(r[1]), "=r"(r[2]), "=r"(r[3]) : "r"(addr));
}
DI void mma_bf16(float d[4], const uint32_t a[4], const uint32_t b[2]) {
    asm volatile(
        "mma.sync.aligned.m16n8k16.row.col.f32.bf16.bf16.f32 "
        "{%0,%1,%2,%3}, {%4,%5,%6,%7}, {%8,%9}, {%0,%1,%2,%3};"
        : "+f"(d[0]), "+f"(d[1]), "+f"(d[2]), "+f"(d[3])
        : "r"(a[0]), "r"(a[1]), "r"(a[2]), "r"(a[3]), "r"(b[0]), "r"(b[1]));
}
DI void cp16(uint32_t dst, const void* src) {
    asm volatile("cp.async.cg.shared.global [%0], [%1], 16;" :: "r"(dst), "l"(src));
}
#define CP_COMMIT() asm volatile("cp.async.commit_group;" ::: "memory")
#define CP_WAIT(n)  asm volatile("cp.async.wait_group %0;" :: "n"(n) : "memory")

// write fp32 value as bf16 hi/lo pair into a slab [row][512] = [hi(256)|lo(256)]
DI void slab_write(__nv_bfloat16* slab, size_t row, int col, float v) {
    __nv_bfloat16 h = __float2bfloat16(v);
    slab[row * 512 + col]       = h;
    slab[row * 512 + 256 + col] = __float2bfloat16(v - __bfloat162float(h));
}

// ============================ static device scratch ============================
__device__ float g_AX [131072 * 1280];          // x-projections f32: [r,u,h,zp,zq]
__device__ float g_U  [4096 * 256];
__device__ float g_HD [4096 * 1024];            // [mu_p | lp | mu_q | lq]
__device__ float g_Hf [2 * 4096 * 256];         // f32 h state (prev/next)
__device__ float g_G  [131072 * 128];
// bf16 hi/lo slabs: [row][512] = [hi|lo]
__device__ __align__(16) __nv_bfloat16 g_Xs  [(size_t)131072 * 512];
__device__ __align__(16) __nv_bfloat16 g_Hseq[(size_t)131072 * 512];
__device__ __align__(16) __nv_bfloat16 g_Zseq[(size_t)131072 * 512];
__device__ __align__(16) __nv_bfloat16 g_Hst [2 * 4096 * 512];
__device__ __align__(16) __nv_bfloat16 g_Zst [2 * 4096 * 512];
__device__ __align__(16) __nv_bfloat16 g_RH  [4096 * 512];
__device__ __align__(16) __nv_bfloat16 g_HZP [4096 * 512];
__device__ __align__(16) __nv_bfloat16 g_HZQ [4096 * 512];
// prepacked weights: bf16 [N][3K] = [hi | hi | lo], transposed, K-major
constexpr size_t O1 = 0;                 // [1280][768]
constexpr size_t O2 = O1 + 1280 * 768;   // [512][1536]
constexpr size_t O3 = O2 + 512 * 1536;   // [256][1536]
constexpr size_t O4 = O3 + 256 * 1536;   // [512][768]
constexpr size_t O5 = O4 + 512 * 768;    // [1024][768]
constexpr size_t O6 = O5 + 1024 * 768;   // [128][2304]
constexpr size_t WTOT = O6 + 128 * 2304;
__device__ __align__(16) __nv_bfloat16 g_Wp[WTOT];

// ============================ A descriptor ============================
// up to 3 slabs of 256 K each; s1 used when nseg>=2 (heads GEMM), else same as s0
struct ADesc { const __nv_bfloat16* s0[3]; const __nv_bfloat16* s1[3]; };

// ============================ Epilogues ============================
struct EP_AX {
    float* AX; const float* bias[5]; const float* yph; const float* WzqY;
    DI void operator()(int row, int col, float acc) const {
        int seg = col >> 8, c = col & 255;
        float v = acc + bias[seg][c];
        if (seg == 4)
            v += yph[(size_t)row * 2] * WzqY[c] + yph[(size_t)row * 2 + 1] * WzqY[256 + c];
        AX[(size_t)row * 1280 + col] = v;
    }
};
struct EP_RU { // r -> RH slab (r*h_prev), u -> f32 U
    const float* AX; const float* hpf; float* U; __nv_bfloat16* RH; int t;
    DI void operator()(int b, int col, float acc) const {
        size_t bt = (size_t)b * Tn + t;
        float pre = acc + AX[bt * 1280 + col];
        if (col < 256) {
            float r = sigf(pre);
            slab_write(RH, b, col, r * hpf[b * 256 + col]);
        } else {
            U[b * 256 + col - 256] = sigf(pre);
        }
    }
};
struct EP_H {
    const float* AX; const float* U; const float* hpf; float* hnf;
    __nv_bfloat16* Hst; __nv_bfloat16* Hseq; int t;
    DI void operator()(int b, int c, float acc) const {
        size_t bt = (size_t)b * Tn + t;
        float ht = tanhf(acc + AX[bt * 1280 + 512 + c]);
        float u  = U[b * 256 + c];
        float h  = (1.0f - u) * hpf[b * 256 + c] + u * ht;
        hnf[b * 256 + c] = h;
        slab_write(Hst, b, c, h);
        slab_write(Hseq, bt, c, h);
    }
};
struct EP_ZPQ {
    const float* AX; __nv_bfloat16* P; __nv_bfloat16* Q; int t;
    DI void operator()(int b, int col, float acc) const {
        size_t bt = (size_t)b * Tn + t;
        if (col < 256) slab_write(P, b, col, tanhf(acc + AX[bt * 1280 + 768 + col]));
        else           slab_write(Q, b, col - 256, tanhf(acc + AX[bt * 1280 + 1024 + (col - 256)]));
    }
};
struct EP_HEADS {
    float* HD; const float* bias[4];
    DI void operator()(int b, int col, float acc) const {
        int seg = col >> 8, c = col & 255;
        HD[(size_t)b * 1024 + col] = acc + bias[seg][c];
    }
};
struct EP_G {
    float* G; const float* bg;
    DI void operator()(int row, int col, float acc) const {
        G[(size_t)row * 128 + col] = tanhf(acc + bg[col]);
    }
};

// ============================ bf16 split mma.sync GEMM ============================
// CTA tile 128x128, BK=32 bf16. K' = 3K ([Ahi|Alo|Ahi] x [Bhi|Bhi|Blo]).
// 8 warps as 2(m) x 4(n): warp tile 64x32; acc[4][4][4].
// SMEM: 3 stages x (A 128x80B + B 128x80B) = 61440 B dynamic, cp.async pipeline.
constexpr int A_TILE = 128 * 80;
constexpr int STAGE  = 2 * A_TILE;       // A + B
constexpr int SMEM_BYTES = 3 * STAGE;

template <class EP>
__global__ __launch_bounds__(256, 2)
void tgemm(ADesc ad, EP ep, const __nv_bfloat16* __restrict__ Bp, int K) {
    extern __shared__ __align__(16) uint8_t smem[];
    const uint32_t sb = smem_u32(smem);

    const int tid  = threadIdx.x;
    const int lane = tid & 31;
    const int warp = tid >> 5;
    const int m0 = blockIdx.y * 128;
    const int n0 = blockIdx.x * 128;
    const int nseg = n0 >> 8;
    const int warpM = (warp >> 2) * 64;
    const int warpN = (warp & 3) * 32;
    const int K3 = 3 * K;
    const int cpt = K >> 5;       // 32-K chunks per split term
    const int nch = 3 * cpt;

    const __nv_bfloat16* const* slabs = (nseg < 2) ? ad.s0 : ad.s1;

    // fill coords: each thread copies 2x16B for A and 2x16B for B
    const int frow = tid >> 1;          // 0..127
    const int fhalf = (tid & 1);        // 0/1 -> 32B half of the 64B row

    float acc[4][4][4];
#pragma unroll
    for (int i = 0; i < 4; i++)
#pragma unroll
        for (int j = 0; j < 4; j++)
#pragma unroll
            for (int q = 0; q < 4; q++) acc[i][j][q] = 0.0f;

    auto fill = [&](int ch, int stg) {
        // A
        int term = ch / cpt;
        int kk = (ch % cpt) * 32 + fhalf * 16;          // bf16 index within K
        int slab = kk >> 8, o = kk & 255;
        const __nv_bfloat16* src = slabs[slab] + (size_t)(m0 + frow) * 512
                                   + (term == 1 ? 256 : 0) + o;
        uint32_t dA = sb + stg * STAGE + frow * 80 + fhalf * 32;
        cp16(dA, src); cp16(dA + 16, src + 8);
        // B
        const __nv_bfloat16* bs = Bp + (size_t)(n0 + frow) * K3 + ch * 32 + fhalf * 16;
        uint32_t dB = sb + stg * STAGE + A_TILE + frow * 80 + fhalf * 32;
        cp16(dB, bs); cp16(dB + 16, bs + 8);
    };

    auto mmastep = [&](int stg) {
        const uint32_t Ab = sb + stg * STAGE;
        const uint32_t Bb = Ab + A_TILE;
#pragma unroll
        for (int ks = 0; ks < 2; ks++) {
            uint32_t afr[4][4];
#pragma unroll
            for (int mf = 0; mf < 4; mf++)
                ldm_x4(afr[mf], Ab + (warpM + mf * 16 + (lane & 15)) * 80
                                   + ((ks << 1) + (lane >> 4)) * 16);
            uint32_t bfr[2][4];
#pragma unroll
            for (int j = 0; j < 2; j++)
                ldm_x4(bfr[j], Bb + (warpN + j * 16 + (lane & 7) + ((lane >> 4) & 1) * 8) * 80
                                  + ((ks << 1) + ((lane >> 3) & 1)) * 16);
#pragma unroll
            for (int mf = 0; mf < 4; mf++)
#pragma unroll
                for (int nf = 0; nf < 4; nf++)
                    mma_bf16(acc[mf][nf], afr[mf], &bfr[nf >> 1][(nf & 1) * 2]);
        }
    };

    fill(0, 0); CP_COMMIT();
    fill(1, 1); CP_COMMIT();

    for (int i = 0; i < nch; i++) {
        if (i + 1 < nch) CP_WAIT(1); else CP_WAIT(0);
        __syncthreads();
        if (i + 2 < nch) { fill(i + 2, (i + 2) % 3); CP_COMMIT(); }
        mmastep(i % 3);
    }

    // register-direct fused epilogue (mma.m16n8k16 C fragment mapping)
#pragma unroll
    for (int mf = 0; mf < 4; mf++)
#pragma unroll
        for (int nf = 0; nf < 4; nf++)
#pragma unroll
            for (int j = 0; j < 4; j++) {
                int m = m0 + warpM + mf * 16 + (lane >> 2) + ((j >> 1) << 3);
                int n = n0 + warpN + (nf >> 1) * 16 + (nf & 1) * 8 + ((lane & 3) << 1) + (j & 1);
                ep(m, n, acc[mf][nf][j]);
            }
}

// ============================ weight prep ============================
__global__ void prep_w(const float* __restrict__ src, int src_ld, int src_row0,
                       __nv_bfloat16* __restrict__ dst, int dst_row0, int Kfull,
                       int kslice0, int Krows, int Ncols) {
    int idx = blockIdx.x * 256 + threadIdx.x;
    if (idx >= Krows * Ncols) return;
    int k = idx / Ncols, n = idx % Ncols;
    float v = src[(size_t)(src_row0 + k) * src_ld + n];
    __nv_bfloat16 hi = __float2bfloat16(v);
    __nv_bfloat16 lo = __float2bfloat16(v - __bfloat162float(hi));
    size_t base = (size_t)(dst_row0 + n) * (3 * Kfull) + kslice0 + k;
    dst[base]             = hi;
    dst[base + Kfull]     = hi;
    dst[base + 2 * Kfull] = lo;
}

// ============================ small kernels ============================
__global__ void init_copy(const float* __restrict__ x, const float* __restrict__ h0,
                          const float* __restrict__ z0, __nv_bfloat16* __restrict__ Xs,
                          float* __restrict__ Hf, __nv_bfloat16* __restrict__ Hst,
                          __nv_bfloat16* __restrict__ Zst) {
    size_t idx = (size_t)blockIdx.x * blockDim.x + threadIdx.x;
    size_t r = idx >> 8;
    int k = (int)(idx & 255);
    slab_write(Xs, r, k, x[idx]);
    if (idx < (size_t)Bn * Hn) {
        float hv = h0[idx], zv = z0[idx];
        Hf[idx] = hv;
        slab_write(Hst, r, k, hv);
        slab_write(Zst, r, k, zv);
    }
}

__global__ void step_latent(const float* __restrict__ HD, const float* __restrict__ eps_t,
                            __nv_bfloat16* __restrict__ Zst, __nv_bfloat16* __restrict__ Zseq,
                            float* __restrict__ outKL, int t) {
    int b = blockIdx.x, c = threadIdx.x;
    size_t hb = (size_t)b * 1024;
    float mup = HD[hb + c];
    float lp  = HD[hb + 256 + c];
    float muq = HD[hb + 512 + c];
    float lq  = HD[hb + 768 + c];
    float z = muq + expf(0.5f * lq) * eps_t[b * 256 + c];
    size_t bt = (size_t)b * Tn + t;
    slab_write(Zst, b, c, z);
    slab_write(Zseq, bt, c, z);
    float d = muq - mup;
    float kl = 0.5f * (lp - lq) + (expf(lq) + d * d) / (2.0f * expf(lp)) - 0.5f;

    __shared__ float red[8];
    for (int o = 16; o; o >>= 1) kl += __shfl_down_sync(0xffffffffu, kl, o);
    if ((threadIdx.x & 31) == 0) red[threadIdx.x >> 5] = kl;
    __syncthreads();
    if (threadIdx.x == 0) {
        float s = 0.0f;
#pragma unroll
        for (int i = 0; i < 8; i++) s += red[i];
        outKL[bt] = s;
    }
}

__global__ void yhead(const float* __restrict__ G, const float* __restrict__ Wy,
                      const float* __restrict__ by, float* __restrict__ outY) {
    int r = blockIdx.x * 8 + (threadIdx.x >> 5);
    int lane = threadIdx.x & 31;
    float s0 = 0.0f, s1 = 0.0f;
    const float* g = G + (size_t)r * 128;
    for (int k = lane; k < 128; k += 32) {
        float gv = g[k];
        s0 += gv * Wy[k * 2];
        s1 += gv * Wy[k * 2 + 1];
    }
    for (int o = 16; o; o >>= 1) {
        s0 += __shfl_down_sync(0xffffffffu, s0, o);
        s1 += __shfl_down_sync(0xffffffffu, s1, o);
    }
    if (lane == 0) {
        float l0 = s0 + by[0], l1 = s1 + by[1];
        float m = fmaxf(l0, l1);
        float e0 = expf(l0 - m), e1 = expf(l1 - m);
        float inv = 1.0f / (e0 + e1);
        outY[(size_t)r * 2]     = e0 * inv;
        outY[(size_t)r * 2 + 1] = e1 * inv;
    }
}

__global__ void gatherGT(const float* __restrict__ G, const int* __restrict__ Tph,
                         float* __restrict__ outGT) {
    int b = blockIdx.x;
    int t = Tph[b] - 1;
    outGT[(size_t)b * Gn + threadIdx.x] = G[((size_t)b * Tn + t) * Gn + threadIdx.x];
}

// ============================ launch ============================
extern "C" void kernel_launch(void* const* d_in, const int* in_sizes, int n_in,
                              void* d_out, int out_size) {
    const float* x   = (const float*)d_in[0];
    const float* yph = (const float*)d_in[1];
    const int*   Tph = (const int*)  d_in[2];
    const float* h0  = (const float*)d_in[3];
    const float* z0  = (const float*)d_in[4];
    const float* eps = (const float*)d_in[5];
    const float* Wr  = (const float*)d_in[6];  const float* br  = (const float*)d_in[7];
    const float* Wu  = (const float*)d_in[8];  const float* bu  = (const float*)d_in[9];
    const float* Wh  = (const float*)d_in[10]; const float* bh  = (const float*)d_in[11];
    const float* Wzp = (const float*)d_in[12]; const float* bzp = (const float*)d_in[13];
    const float* Wpm = (const float*)d_in[14]; const float* bpm = (const float*)d_in[15];
    const float* Wps = (const float*)d_in[16]; const float* bps = (const float*)d_in[17];
    const float* Wzq = (const float*)d_in[18]; const float* bzq = (const float*)d_in[19];
    const float* Wqm = (const float*)d_in[20]; const float* bqm = (const float*)d_in[21];
    const float* Wqs = (const float*)d_in[22]; const float* bqs = (const float*)d_in[23];
    const float* Wg  = (const float*)d_in[24]; const float* bg  = (const float*)d_in[25];
    const float* Wy  = (const float*)d_in[26]; const float* by  = (const float*)d_in[27];

    float *AX, *U, *HD, *Hf, *Gb;
    __nv_bfloat16 *Xs, *Hseq, *Zseq, *Hst, *Zst, *RH, *HZP, *HZQ, *Wp;
    {
        void* p;
        cudaGetSymbolAddress(&p, g_AX);   AX   = (float*)p;
        cudaGetSymbolAddress(&p, g_U);    U    = (float*)p;
        cudaGetSymbolAddress(&p, g_HD);   HD   = (float*)p;
        cudaGetSymbolAddress(&p, g_Hf);   Hf   = (float*)p;
        cudaGetSymbolAddress(&p, g_G);    Gb   = (float*)p;
        cudaGetSymbolAddress(&p, g_Xs);   Xs   = (__nv_bfloat16*)p;
        cudaGetSymbolAddress(&p, g_Hseq); Hseq = (__nv_bfloat16*)p;
        cudaGetSymbolAddress(&p, g_Zseq); Zseq = (__nv_bfloat16*)p;
        cudaGetSymbolAddress(&p, g_Hst);  Hst  = (__nv_bfloat16*)p;
        cudaGetSymbolAddress(&p, g_Zst);  Zst  = (__nv_bfloat16*)p;
        cudaGetSymbolAddress(&p, g_RH);   RH   = (__nv_bfloat16*)p;
        cudaGetSymbolAddress(&p, g_HZP);  HZP  = (__nv_bfloat16*)p;
        cudaGetSymbolAddress(&p, g_HZQ);  HZQ  = (__nv_bfloat16*)p;
        cudaGetSymbolAddress(&p, g_Wp);   Wp   = (__nv_bfloat16*)p;
    }

    cudaFuncSetAttribute((const void*)tgemm<EP_AX>,    cudaFuncAttributeMaxDynamicSharedMemorySize, SMEM_BYTES);
    cudaFuncSetAttribute((const void*)tgemm<EP_RU>,    cudaFuncAttributeMaxDynamicSharedMemorySize, SMEM_BYTES);
    cudaFuncSetAttribute((const void*)tgemm<EP_H>,     cudaFuncAttributeMaxDynamicSharedMemorySize, SMEM_BYTES);
    cudaFuncSetAttribute((const void*)tgemm<EP_ZPQ>,   cudaFuncAttributeMaxDynamicSharedMemorySize, SMEM_BYTES);
    cudaFuncSetAttribute((const void*)tgemm<EP_HEADS>, cudaFuncAttributeMaxDynamicSharedMemorySize, SMEM_BYTES);
    cudaFuncSetAttribute((const void*)tgemm<EP_G>,     cudaFuncAttributeMaxDynamicSharedMemorySize, SMEM_BYTES);

    float* out   = (float*)d_out;
    float* outY  = out;
    float* outKL = out + (size_t)BT * Yn;
    float* outGT = out + (size_t)BT * Yn + BT;

    // ---- weight prep: transpose + bf16 hi/lo split into [N][3K] ----
    auto prep = [&](const float* src, int src_ld, int src_row0, size_t dst_off,
                    int dst_row0, int Kfull, int kslice0, int Krows, int Ncols) {
        int tot = Krows * Ncols;
        prep_w<<<(tot + 255) / 256, 256>>>(src, src_ld, src_row0, Wp + dst_off,
                                           dst_row0, Kfull, kslice0, Krows, Ncols);
    };
    prep(Wr,  256, 0, O1,    0, 256, 0, 256, 256);
    prep(Wu,  256, 0, O1,  256, 256, 0, 256, 256);
    prep(Wh,  256, 0, O1,  512, 256, 0, 256, 256);
    prep(Wzp, 256, 0, O1,  768, 256, 0, 256, 256);
    prep(Wzq, 256, 0, O1, 1024, 256, 0, 256, 256);
    prep(Wr,  256, 256, O2,   0, 512, 0, 512, 256);
    prep(Wu,  256, 256, O2, 256, 512, 0, 512, 256);
    prep(Wh,  256, 256, O3,   0, 512, 0, 512, 256);
    prep(Wzp, 256, 256, O4,   0, 256, 0, 256, 256);
    prep(Wzq, 256, 256, O4, 256, 256, 0, 256, 256);
    prep(Wpm, 256, 0, O5,   0, 256, 0, 256, 256);
    prep(Wps, 256, 0, O5, 256, 256, 0, 256, 256);
    prep(Wqm, 256, 0, O5, 512, 256, 0, 256, 256);
    prep(Wqs, 256, 0, O5, 768, 256, 0, 256, 256);
    prep(Wg,  128, 0, O6,   0, 768, 0, 768, 128);

    init_copy<<<BT, 256>>>(x, h0, z0, Xs, Hf, Hst, Zst);

    dim3 blk(256);

    // phase 1: x-projections  [131072,256(x3)] @ -> N=1280
    {
        ADesc ad{}; ad.s0[0] = Xs; ad.s1[0] = Xs;
        EP_AX ep;
        ep.AX = AX;
        ep.bias[0] = br; ep.bias[1] = bu; ep.bias[2] = bh; ep.bias[3] = bzp; ep.bias[4] = bzq;
        ep.yph = yph; ep.WzqY = Wzq + 512 * 256;
        tgemm<<<dim3(1280 / 128, BT / 128), blk, SMEM_BYTES>>>(ad, ep, Wp + O1, 256);
    }

    // phase 2: sequential scan
    for (int t = 0; t < Tn; t++) {
        int cur = t & 1, nxt = cur ^ 1;
        const float* hpf = Hf + (size_t)cur * Bn * Hn;
        float* hnf       = Hf + (size_t)nxt * Bn * Hn;
        __nv_bfloat16* HstC = Hst + (size_t)cur * Bn * 512;
        __nv_bfloat16* HstN = Hst + (size_t)nxt * Bn * 512;
        __nv_bfloat16* ZstC = Zst + (size_t)cur * Bn * 512;
        __nv_bfloat16* ZstN = Zst + (size_t)nxt * Bn * 512;

        { // gates r,u: A = [h_prev | z_prev], N=512
            ADesc ad{}; ad.s0[0] = HstC; ad.s0[1] = ZstC; ad.s1[0] = HstC; ad.s1[1] = ZstC;
            EP_RU ep{AX, hpf, U, RH, t};
            tgemm<<<dim3(512 / 128, Bn / 128), blk, SMEM_BYTES>>>(ad, ep, Wp + O2, 512);
        }
        { // candidate + GRU update: A = [r*h_prev | z_prev], N=256
            ADesc ad{}; ad.s0[0] = RH; ad.s0[1] = ZstC; ad.s1[0] = RH; ad.s1[1] = ZstC;
            EP_H ep{AX, U, hpf, hnf, HstN, Hseq, t};
            tgemm<<<dim3(256 / 128, Bn / 128), blk, SMEM_BYTES>>>(ad, ep, Wp + O3, 512);
        }
        { // latent hiddens: A = h_new, N=512
            ADesc ad{}; ad.s0[0] = HstN; ad.s1[0] = HstN;
            EP_ZPQ ep{AX, HZP, HZQ, t};
            tgemm<<<dim3(512 / 128, Bn / 128), blk, SMEM_BYTES>>>(ad, ep, Wp + O4, 256);
        }
        { // heads: N=1024, A = HZP for segs 0-1, HZQ for segs 2-3
            ADesc ad{}; ad.s0[0] = HZP; ad.s1[0] = HZQ;
            EP_HEADS ep;
            ep.HD = HD;
            ep.bias[0] = bpm; ep.bias[1] = bps; ep.bias[2] = bqm; ep.bias[3] = bqs;
            tgemm<<<dim3(1024 / 128, Bn / 128), blk, SMEM_BYTES>>>(ad, ep, Wp + O5, 256);
        }
        step_latent<<<Bn, 256>>>(HD, eps + (size_t)t * Bn * Zn, ZstN, Zseq, outKL, t);
    }

    // phase 3: g = tanh([x|h|z] @ Wg + bg), N=128
    {
        ADesc ad{}; ad.s0[0] = Xs; ad.s0[1] = Hseq; ad.s0[2] = Zseq;
        ad.s1[0] = Xs; ad.s1[1] = Hseq; ad.s1[2] = Zseq;
        EP_G ep{Gb, bg};
        tgemm<<<dim3(Gn / 128, BT / 128), blk, SMEM_BYTES>>>(ad, ep, Wp + O6, 768);
    }
    yhead<<<BT / 8, 256>>>(Gb, Wy, by, outY);
    gatherGT<<<Bn, Gn>>>(Gb, Tph, outGT);
}

// round 6
// speedup vs baseline: 1.5976x; 1.2353x over previous
#include <cuda_runtime.h>
#include <cuda_fp16.h>
#include <math.h>
#include <cstdint>

// Problem constants (fixed by the dataset)
constexpr int Bn = 4096, Tn = 32, Xn = 256, Hn = 256, Zn = 256, Gn = 128, Yn = 2;
constexpr int BT = Bn * Tn; // 131072

#define DI __device__ __forceinline__

DI uint32_t smem_u32(const void* p) {
    uint32_t a;
    asm("{ .reg .u64 t; cvta.to.shared.u64 t, %1; cvt.u32.u64 %0, t; }" : "=r"(a) : "l"(p));
    return a;
}
DI float sigf(float x) { return 1.0f / (1.0f + expf(-x)); }

DI void ldm_x4(uint32_t r[4], uint32_t addr) {
    asm volatile("ldmatrix.sync.aligned.m8n8.x4.shared.b16 {%0,%1,%2,%3}, [%4];"
                 : "=r"(r[0]), "=r"(r[1]), "=r"(r[2]), "=r"(r[3]) : "r"(addr));
}
DI void mma_f16(float d[4], const uint32_t a[4], const uint32_t b[2]) {
    asm volatile(
        "mma.sync.aligned.m16n8k16.row.col.f32.f16.f16.f32 "
        "{%0,%1,%2,%3}, {%4,%5,%6,%7}, {%8,%9}, {%0,%1,%2,%3};"
        : "+f"(d[0]), "+f"(d[1]), "+f"(d[2]), "+f"(d[3])
        : "r"(a[0]), "r"(a[1]), "r"(a[2]), "r"(a[3]), "r"(b[0]), "r"(b[1]));
}
DI void cp16(uint32_t dst, const void* src) {
    asm volatile("cp.async.cg.shared.global [%0], [%1], 16;" :: "r"(dst), "l"(src));
}
#define CP_COMMIT() asm volatile("cp.async.commit_group;" ::: "memory")
#define CP_WAIT(n)  asm volatile("cp.async.wait_group %0;" :: "n"(n) : "memory")

// write fp32 value as fp16 hi/lo pair into a slab [row][512] = [hi(256)|lo(256)]
DI void slab_write(__half* slab, size_t row, int col, float v) {
    __half h = __float2half_rn(v);
    slab[row * 512 + col]       = h;
    slab[row * 512 + 256 + col] = __float2half_rn(v - __half2float(h));
}

// ============================ static device scratch ============================
__device__ float g_AX [131072 * 1280];          // x-projections f32: [r,u,h,zp,zq]
__device__ float g_U  [4096 * 256];
__device__ float g_HD [4096 * 1024];            // [mu_p | lp | mu_q | lq]
__device__ float g_Hf [2 * 4096 * 256];         // f32 h state (prev/next)
__device__ float g_G  [131072 * 128];
// fp16 hi/lo slabs: [row][512] = [hi|lo]
__device__ __align__(16) __half g_Xs  [(size_t)131072 * 512];
__device__ __align__(16) __half g_Hseq[(size_t)131072 * 512];
__device__ __align__(16) __half g_Zseq[(size_t)131072 * 512];
__device__ __align__(16) __half g_Hst [2 * 4096 * 512];
__device__ __align__(16) __half g_Zst [2 * 4096 * 512];
__device__ __align__(16) __half g_RH  [4096 * 512];
__device__ __align__(16) __half g_HZP [4096 * 512];
__device__ __align__(16) __half g_HZQ [4096 * 512];
// prepacked weights: fp16 hi only, transposed, [N][K] K-major
constexpr size_t O1 = 0;                  // [1280][256]
constexpr size_t O2 = O1 + 1280 * 256;    // [512][512]
constexpr size_t O3 = O2 + 512 * 512;     // [256][512]
constexpr size_t O4 = O3 + 256 * 512;     // [512][256]
constexpr size_t O5 = O4 + 512 * 256;     // [1024][256]
constexpr size_t O6 = O5 + 1024 * 256;    // [128][768]
constexpr size_t WTOT = O6 + 128 * 768;
__device__ __align__(16) __half g_Wp[WTOT];

// ============================ A descriptor ============================
struct ADesc { const __half* s0[3]; const __half* s1[3]; };

// ============================ Epilogues ============================
struct EP_AX {
    float* AX; const float* bias[5]; const float* yph; const float* WzqY;
    DI void operator()(int row, int col, float acc) const {
        int seg = col >> 8, c = col & 255;
        float v = acc + bias[seg][c];
        if (seg == 4)
            v += yph[(size_t)row * 2] * WzqY[c] + yph[(size_t)row * 2 + 1] * WzqY[256 + c];
        AX[(size_t)row * 1280 + col] = v;
    }
};
struct EP_RU { // r -> RH slab (r*h_prev), u -> f32 U
    const float* AX; const float* hpf; float* U; __half* RH; int t;
    DI void operator()(int b, int col, float acc) const {
        size_t bt = (size_t)b * Tn + t;
        float pre = acc + AX[bt * 1280 + col];
        if (col < 256) {
            float r = sigf(pre);
            slab_write(RH, b, col, r * hpf[b * 256 + col]);
        } else {
            U[b * 256 + col - 256] = sigf(pre);
        }
    }
};
struct EP_H {
    const float* AX; const float* U; const float* hpf; float* hnf;
    __half* Hst; __half* Hseq; int t;
    DI void operator()(int b, int c, float acc) const {
        size_t bt = (size_t)b * Tn + t;
        float ht = tanhf(acc + AX[bt * 1280 + 512 + c]);
        float u  = U[b * 256 + c];
        float h  = (1.0f - u) * hpf[b * 256 + c] + u * ht;
        hnf[b * 256 + c] = h;
        slab_write(Hst, b, c, h);
        slab_write(Hseq, bt, c, h);
    }
};
struct EP_ZPQ {
    const float* AX; __half* P; __half* Q; int t;
    DI void operator()(int b, int col, float acc) const {
        size_t bt = (size_t)b * Tn + t;
        if (col < 256) slab_write(P, b, col, tanhf(acc + AX[bt * 1280 + 768 + col]));
        else           slab_write(Q, b, col - 256, tanhf(acc + AX[bt * 1280 + 1024 + (col - 256)]));
    }
};
struct EP_HEADS {
    float* HD; const float* bias[4];
    DI void operator()(int b, int col, float acc) const {
        int seg = col >> 8, c = col & 255;
        HD[(size_t)b * 1024 + col] = acc + bias[seg][c];
    }
};
struct EP_G {
    float* G; const float* bg;
    DI void operator()(int row, int col, float acc) const {
        G[(size_t)row * 128 + col] = tanhf(acc + bg[col]);
    }
};

// ============================ fp16 2-term split mma.sync GEMM ============================
// CTA tile 128x128, BK=32 fp16. K' = 2K: term0 = Ahi x Bhi, term1 = Alo x Bhi.
// 8 warps as 2(m) x 4(n): warp tile 64x32; acc[4][4][4].
// SMEM: 4 stages x (A 128x80B + B 128x80B) = 81920 B dynamic, cp.async pipeline.
constexpr int A_TILE = 128 * 80;
constexpr int STAGE  = 2 * A_TILE;
constexpr int NSTG   = 4;
constexpr int SMEM_BYTES = NSTG * STAGE;

template <class EP>
__global__ __launch_bounds__(256, 2)
void tgemm(ADesc ad, EP ep, const __half* __restrict__ Bp, int K) {
    extern __shared__ __align__(16) uint8_t smem[];
    const uint32_t sb = smem_u32(smem);

    const int tid  = threadIdx.x;
    const int lane = tid & 31;
    const int warp = tid >> 5;
    const int m0 = blockIdx.y * 128;
    const int n0 = blockIdx.x * 128;
    const int nseg = n0 >> 8;
    const int warpM = (warp >> 2) * 64;
    const int warpN = (warp & 3) * 32;
    const int cpt = K >> 5;       // 32-K chunks per split term
    const int nch = 2 * cpt;

    const __half* const* slabs = (nseg < 2) ? ad.s0 : ad.s1;

    const int frow = tid >> 1;          // 0..127
    const int fhalf = (tid & 1);        // 0/1 -> 32B half of the 64B row

    float acc[4][4][4];
#pragma unroll
    for (int i = 0; i < 4; i++)
#pragma unroll
        for (int j = 0; j < 4; j++)
#pragma unroll
            for (int q = 0; q < 4; q++) acc[i][j][q] = 0.0f;

    auto fill = [&](int ch, int stg) {
        // A: term 0 reads hi (offset 0), term 1 reads lo (offset 256)
        int term = ch >= cpt;
        int kk = (term ? ch - cpt : ch) * 32 + fhalf * 16;
        int slab = kk >> 8, o = kk & 255;
        const __half* src = slabs[slab] + (size_t)(m0 + frow) * 512 + term * 256 + o;
        uint32_t dA = sb + stg * STAGE + frow * 80 + fhalf * 32;
        cp16(dA, src); cp16(dA + 16, src + 8);
        // B: hi only, both terms
        int chk = term ? ch - cpt : ch;
        const __half* bs = Bp + (size_t)(n0 + frow) * K + chk * 32 + fhalf * 16;
        uint32_t dB = sb + stg * STAGE + A_TILE + frow * 80 + fhalf * 32;
        cp16(dB, bs); cp16(dB + 16, bs + 8);
    };

    auto mmastep = [&](int stg) {
        const uint32_t Ab = sb + stg * STAGE;
        const uint32_t Bb = Ab + A_TILE;
#pragma unroll
        for (int ks = 0; ks < 2; ks++) {
            uint32_t afr[4][4];
#pragma unroll
            for (int mf = 0; mf < 4; mf++)
                ldm_x4(afr[mf], Ab + (warpM + mf * 16 + (lane & 15)) * 80
                                   + ((ks << 1) + (lane >> 4)) * 16);
            uint32_t bfr[2][4];
#pragma unroll
            for (int j = 0; j < 2; j++)
                ldm_x4(bfr[j], Bb + (warpN + j * 16 + (lane & 7) + ((lane >> 4) & 1) * 8) * 80
                                  + ((ks << 1) + ((lane >> 3) & 1)) * 16);
#pragma unroll
            for (int mf = 0; mf < 4; mf++)
#pragma unroll
                for (int nf = 0; nf < 4; nf++)
                    mma_f16(acc[mf][nf], afr[mf], &bfr[nf >> 1][(nf & 1) * 2]);
        }
    };

    fill(0, 0); CP_COMMIT();
    fill(1, 1); CP_COMMIT();
    fill(2, 2); CP_COMMIT();

    for (int i = 0; i < nch; i++) {
        if (i + 3 <= nch)      CP_WAIT(2);
        else if (i + 2 == nch) CP_WAIT(1);
        else                   CP_WAIT(0);
        __syncthreads();
        if (i + 3 < nch) { fill(i + 3, (i + 3) & 3); CP_COMMIT(); }
        mmastep(i & 3);
    }

    // register-direct fused epilogue (mma.m16n8k16 C fragment mapping)
#pragma unroll
    for (int mf = 0; mf < 4; mf++)
#pragma unroll
        for (int nf = 0; nf < 4; nf++)
#pragma unroll
            for (int j = 0; j < 4; j++) {
                int m = m0 + warpM + mf * 16 + (lane >> 2) + ((j >> 1) << 3);
                int n = n0 + warpN + (nf >> 1) * 16 + (nf & 1) * 8 + ((lane & 3) << 1) + (j & 1);
                ep(m, n, acc[mf][nf][j]);
            }
}

// ============================ fused weight prep ============================
struct PrepSrc { const float* w[10]; }; // Wr,Wu,Wh,Wzp,Wzq,Wpm,Wps,Wqm,Wqs,Wg

__global__ void prep_all(PrepSrc ps, __half* __restrict__ dst) {
    // slice table: srcIdx, src_ld, src_row0, dst_off, dst_row0, Kfull(=K), N
    struct S { int si, sld, sr0; size_t doff; int dr0, K, N; };
    const S tab[15] = {
        {0, 256,   0, O1,    0, 256, 256}, {1, 256,   0, O1,  256, 256, 256},
        {2, 256,   0, O1,  512, 256, 256}, {3, 256,   0, O1,  768, 256, 256},
        {4, 256,   0, O1, 1024, 256, 256},
        {0, 256, 256, O2,    0, 512, 256}, {1, 256, 256, O2,  256, 512, 256},
        {2, 256, 256, O3,    0, 512, 256},
        {3, 256, 256, O4,    0, 256, 256}, {4, 256, 256, O4,  256, 256, 256},
        {5, 256,   0, O5,    0, 256, 256}, {6, 256,   0, O5,  256, 256, 256},
        {7, 256,   0, O5,  512, 256, 256}, {8, 256,   0, O5,  768, 256, 256},
        {9, 128,   0, O6,    0, 768, 128},
    };
    const int cnt[15] = {65536,65536,65536,65536,65536, 131072,131072, 131072,
                         65536,65536, 65536,65536,65536,65536, 98304};
    int e = blockIdx.x * 256 + threadIdx.x;
    if (e >= 1212416) return;
    // FIXED: stop at the owning slice (previous version kept scanning and
    // misrouted elements of the 131072-sized slices into later slices)
    int s = 14;
    int base = 0;
#pragma unroll
    for (int i = 0; i < 15; i++) {
        int nb = base + cnt[i];
        if (e < nb) { s = i; break; }
        base = nb;
    }
    const S& t = tab[s];
    int local = e - base;
    int k = local / t.N, n = local % t.N;
    float v = ps.w[t.si][(size_t)(t.sr0 + k) * t.sld + n];
    dst[t.doff + (size_t)(t.dr0 + n) * t.K + k] = __float2half_rn(v);
}

// ============================ small kernels ============================
__global__ void init_copy(const float* __restrict__ x, const float* __restrict__ h0,
                          const float* __restrict__ z0, __half* __restrict__ Xs,
                          float* __restrict__ Hf, __half* __restrict__ Hst,
                          __half* __restrict__ Zst) {
    size_t idx = (size_t)blockIdx.x * blockDim.x + threadIdx.x;
    size_t r = idx >> 8;
    int k = (int)(idx & 255);
    slab_write(Xs, r, k, x[idx]);
    if (idx < (size_t)Bn * Hn) {
        float hv = h0[idx], zv = z0[idx];
        Hf[idx] = hv;
        slab_write(Hst, r, k, hv);
        slab_write(Zst, r, k, zv);
    }
}

__global__ void step_latent(const float* __restrict__ HD, const float* __restrict__ eps_t,
                            __half* __restrict__ Zst, __half* __restrict__ Zseq,
                            float* __restrict__ outKL, int t) {
    int b = blockIdx.x, c = threadIdx.x;
    size_t hb = (size_t)b * 1024;
    float mup = HD[hb + c];
    float lp  = HD[hb + 256 + c];
    float muq = HD[hb + 512 + c];
    float lq  = HD[hb + 768 + c];
    float z = muq + expf(0.5f * lq) * eps_t[b * 256 + c];
    size_t bt = (size_t)b * Tn + t;
    slab_write(Zst, b, c, z);
    slab_write(Zseq, bt, c, z);
    float d = muq - mup;
    float kl = 0.5f * (lp - lq) + (expf(lq) + d * d) / (2.0f * expf(lp)) - 0.5f;

    __shared__ float red[8];
    for (int o = 16; o; o >>= 1) kl += __shfl_down_sync(0xffffffffu, kl, o);
    if ((threadIdx.x & 31) == 0) red[threadIdx.x >> 5] = kl;
    __syncthreads();
    if (threadIdx.x == 0) {
        float s = 0.0f;
#pragma unroll
        for (int i = 0; i < 8; i++) s += red[i];
        outKL[bt] = s;
    }
}

__global__ void yhead(const float* __restrict__ G, const float* __restrict__ Wy,
                      const float* __restrict__ by, float* __restrict__ outY) {
    int r = blockIdx.x * 8 + (threadIdx.x >> 5);
    int lane = threadIdx.x & 31;
    float s0 = 0.0f, s1 = 0.0f;
    const float* g = G + (size_t)r * 128;
    for (int k = lane; k < 128; k += 32) {
        float gv = g[k];
        s0 += gv * Wy[k * 2];
        s1 += gv * Wy[k * 2 + 1];
    }
    for (int o = 16; o; o >>= 1) {
        s0 += __shfl_down_sync(0xffffffffu, s0, o);
        s1 += __shfl_down_sync(0xffffffffu, s1, o);
    }
    if (lane == 0) {
        float l0 = s0 + by[0], l1 = s1 + by[1];
        float m = fmaxf(l0, l1);
        float e0 = expf(l0 - m), e1 = expf(l1 - m);
        float inv = 1.0f / (e0 + e1);
        outY[(size_t)r * 2]     = e0 * inv;
        outY[(size_t)r * 2 + 1] = e1 * inv;
    }
}

__global__ void gatherGT(const float* __restrict__ G, const int* __restrict__ Tph,
                         float* __restrict__ outGT) {
    int b = blockIdx.x;
    int t = Tph[b] - 1;
    outGT[(size_t)b * Gn + threadIdx.x] = G[((size_t)b * Tn + t) * Gn + threadIdx.x];
}

// ============================ launch ============================
extern "C" void kernel_launch(void* const* d_in, const int* in_sizes, int n_in,
                              void* d_out, int out_size) {
    const float* x   = (const float*)d_in[0];
    const float* yph = (const float*)d_in[1];
    const int*   Tph = (const int*)  d_in[2];
    const float* h0  = (const float*)d_in[3];
    const float* z0  = (const float*)d_in[4];
    const float* eps = (const float*)d_in[5];
    const float* Wr  = (const float*)d_in[6];  const float* br  = (const float*)d_in[7];
    const float* Wu  = (const float*)d_in[8];  const float* bu  = (const float*)d_in[9];
    const float* Wh  = (const float*)d_in[10]; const float* bh  = (const float*)d_in[11];
    const float* Wzp = (const float*)d_in[12]; const float* bzp = (const float*)d_in[13];
    const float* Wpm = (const float*)d_in[14]; const float* bpm = (const float*)d_in[15];
    const float* Wps = (const float*)d_in[16]; const float* bps = (const float*)d_in[17];
    const float* Wzq = (const float*)d_in[18]; const float* bzq = (const float*)d_in[19];
    const float* Wqm = (const float*)d_in[20]; const float* bqm = (const float*)d_in[21];
    const float* Wqs = (const float*)d_in[22]; const float* bqs = (const float*)d_in[23];
    const float* Wg  = (const float*)d_in[24]; const float* bg  = (const float*)d_in[25];
    const float* Wy  = (const float*)d_in[26]; const float* by  = (const float*)d_in[27];

    float *AX, *U, *HD, *Hf, *Gb;
    __half *Xs, *Hseq, *Zseq, *Hst, *Zst, *RH, *HZP, *HZQ, *Wp;
    {
        void* p;
        cudaGetSymbolAddress(&p, g_AX);   AX   = (float*)p;
        cudaGetSymbolAddress(&p, g_U);    U    = (float*)p;
        cudaGetSymbolAddress(&p, g_HD);   HD   = (float*)p;
        cudaGetSymbolAddress(&p, g_Hf);   Hf   = (float*)p;
        cudaGetSymbolAddress(&p, g_G);    Gb   = (float*)p;
        cudaGetSymbolAddress(&p, g_Xs);   Xs   = (__half*)p;
        cudaGetSymbolAddress(&p, g_Hseq); Hseq = (__half*)p;
        cudaGetSymbolAddress(&p, g_Zseq); Zseq = (__half*)p;
        cudaGetSymbolAddress(&p, g_Hst);  Hst  = (__half*)p;
        cudaGetSymbolAddress(&p, g_Zst);  Zst  = (__half*)p;
        cudaGetSymbolAddress(&p, g_RH);   RH   = (__half*)p;
        cudaGetSymbolAddress(&p, g_HZP);  HZP  = (__half*)p;
        cudaGetSymbolAddress(&p, g_HZQ);  HZQ  = (__half*)p;
        cudaGetSymbolAddress(&p, g_Wp);   Wp   = (__half*)p;
    }

    cudaFuncSetAttribute((const void*)tgemm<EP_AX>,    cudaFuncAttributeMaxDynamicSharedMemorySize, SMEM_BYTES);
    cudaFuncSetAttribute((const void*)tgemm<EP_RU>,    cudaFuncAttributeMaxDynamicSharedMemorySize, SMEM_BYTES);
    cudaFuncSetAttribute((const void*)tgemm<EP_H>,     cudaFuncAttributeMaxDynamicSharedMemorySize, SMEM_BYTES);
    cudaFuncSetAttribute((const void*)tgemm<EP_ZPQ>,   cudaFuncAttributeMaxDynamicSharedMemorySize, SMEM_BYTES);
    cudaFuncSetAttribute((const void*)tgemm<EP_HEADS>, cudaFuncAttributeMaxDynamicSharedMemorySize, SMEM_BYTES);
    cudaFuncSetAttribute((const void*)tgemm<EP_G>,     cudaFuncAttributeMaxDynamicSharedMemorySize, SMEM_BYTES);

    float* out   = (float*)d_out;
    float* outY  = out;
    float* outKL = out + (size_t)BT * Yn;
    float* outGT = out + (size_t)BT * Yn + BT;

    // ---- single fused weight prep ----
    {
        PrepSrc ps;
        ps.w[0] = Wr; ps.w[1] = Wu; ps.w[2] = Wh; ps.w[3] = Wzp; ps.w[4] = Wzq;
        ps.w[5] = Wpm; ps.w[6] = Wps; ps.w[7] = Wqm; ps.w[8] = Wqs; ps.w[9] = Wg;
        prep_all<<<(1212416 + 255) / 256, 256>>>(ps, Wp);
    }

    init_copy<<<BT, 256>>>(x, h0, z0, Xs, Hf, Hst, Zst);

    dim3 blk(256);

    // phase 1: x-projections  -> N=1280, K=256
    {
        ADesc ad{}; ad.s0[0] = Xs; ad.s1[0] = Xs;
        EP_AX ep;
        ep.AX = AX;
        ep.bias[0] = br; ep.bias[1] = bu; ep.bias[2] = bh; ep.bias[3] = bzp; ep.bias[4] = bzq;
        ep.yph = yph; ep.WzqY = Wzq + 512 * 256;
        tgemm<<<dim3(1280 / 128, BT / 128), blk, SMEM_BYTES>>>(ad, ep, Wp + O1, 256);
    }

    // phase 2: sequential scan
    for (int t = 0; t < Tn; t++) {
        int cur = t & 1, nxt = cur ^ 1;
        const float* hpf = Hf + (size_t)cur * Bn * Hn;
        float* hnf       = Hf + (size_t)nxt * Bn * Hn;
        __half* HstC = Hst + (size_t)cur * Bn * 512;
        __half* HstN = Hst + (size_t)nxt * Bn * 512;
        __half* ZstC = Zst + (size_t)cur * Bn * 512;
        __half* ZstN = Zst + (size_t)nxt * Bn * 512;

        { // gates r,u: A = [h_prev | z_prev], N=512, K=512
            ADesc ad{}; ad.s0[0] = HstC; ad.s0[1] = ZstC; ad.s1[0] = HstC; ad.s1[1] = ZstC;
            EP_RU ep{AX, hpf, U, RH, t};
            tgemm<<<dim3(512 / 128, Bn / 128), blk, SMEM_BYTES>>>(ad, ep, Wp + O2, 512);
        }
        { // candidate + GRU update: A = [r*h_prev | z_prev], N=256, K=512
            ADesc ad{}; ad.s0[0] = RH; ad.s0[1] = ZstC; ad.s1[0] = RH; ad.s1[1] = ZstC;
            EP_H ep{AX, U, hpf, hnf, HstN, Hseq, t};
            tgemm<<<dim3(256 / 128, Bn / 128), blk, SMEM_BYTES>>>(ad, ep, Wp + O3, 512);
        }
        { // latent hiddens: A = h_new, N=512, K=256
            ADesc ad{}; ad.s0[0] = HstN; ad.s1[0] = HstN;
            EP_ZPQ ep{AX, HZP, HZQ, t};
            tgemm<<<dim3(512 / 128, Bn / 128), blk, SMEM_BYTES>>>(ad, ep, Wp + O4, 256);
        }
        { // heads: N=1024, K=256; A = HZP for segs 0-1, HZQ for segs 2-3
            ADesc ad{}; ad.s0[0] = HZP; ad.s1[0] = HZQ;
            EP_HEADS ep;
            ep.HD = HD;
            ep.bias[0] = bpm; ep.bias[1] = bps; ep.bias[2] = bqm; ep.bias[3] = bqs;
            tgemm<<<dim3(1024 / 128, Bn / 128), blk, SMEM_BYTES>>>(ad, ep, Wp + O5, 256);
        }
        step_latent<<<Bn, 256>>>(HD, eps + (size_t)t * Bn * Zn, ZstN, Zseq, outKL, t);
    }

    // phase 3: g = tanh([x|h|z] @ Wg + bg), N=128, K=768
    {
        ADesc ad{}; ad.s0[0] = Xs; ad.s0[1] = Hseq; ad.s0[2] = Zseq;
        ad.s1[0] = Xs; ad.s1[1] = Hseq; ad.s1[2] = Zseq;
        EP_G ep{Gb, bg};
        tgemm<<<dim3(Gn / 128, BT / 128), blk, SMEM_BYTES>>>(ad, ep, Wp + O6, 768);
    }
    yhead<<<BT / 8, 256>>>(Gb, Wy, by, outY);
    gatherGT<<<Bn, Gn>>>(Gb, Tph, outGT);
}

// round 7
// speedup vs baseline: 2.0978x; 1.3130x over previous
#include <cuda_runtime.h>
#include <cuda_fp16.h>
#include <math.h>
#include <cstdint>

// Problem constants (fixed by the dataset)
constexpr int Bn = 4096, Tn = 32, Xn = 256, Hn = 256, Zn = 256, Gn = 128, Yn = 2;
constexpr int BT = Bn * Tn; // 131072

#define DI __device__ __forceinline__

DI uint32_t smem_u32(const void* p) {
    uint32_t a;
    asm("{ .reg .u64 t; cvta.to.shared.u64 t, %1; cvt.u32.u64 %0, t; }" : "=r"(a) : "l"(p));
    return a;
}
DI float sigf(float x) { return 1.0f / (1.0f + expf(-x)); }

DI void ldm_x4(uint32_t r[4], uint32_t addr) {
    asm volatile("ldmatrix.sync.aligned.m8n8.x4.shared.b16 {%0,%1,%2,%3}, [%4];"
                 : "=r"(r[0]), "=r"(r[1]), "=r"(r[2]), "=r"(r[3]) : "r"(addr));
}
DI void mma_f16(float d[4], const uint32_t a[4], const uint32_t b[2]) {
    asm volatile(
        "mma.sync.aligned.m16n8k16.row.col.f32.f16.f16.f32 "
        "{%0,%1,%2,%3}, {%4,%5,%6,%7}, {%8,%9}, {%0,%1,%2,%3};"
        : "+f"(d[0]), "+f"(d[1]), "+f"(d[2]), "+f"(d[3])
        : "r"(a[0]), "r"(a[1]), "r"(a[2]), "r"(a[3]), "r"(b[0]), "r"(b[1]));
}
DI void cp16(uint32_t dst, const void* src) {
    asm volatile("cp.async.cg.shared.global [%0], [%1], 16;" :: "r"(dst), "l"(src));
}
#define CP_COMMIT() asm volatile("cp.async.commit_group;" ::: "memory")
#define CP_WAIT(n)  asm volatile("cp.async.wait_group %0;" :: "n"(n) : "memory")

// write fp32 value as fp16 hi/lo pair into a slab [row][512] = [hi(256)|lo(256)]
DI void slab_write(__half* slab, size_t row, int col, float v) {
    __half h = __float2half_rn(v);
    slab[row * 512 + col]       = h;
    slab[row * 512 + 256 + col] = __float2half_rn(v - __half2float(h));
}

// ============================ static device scratch ============================
__device__ float g_AX [131072 * 1280];          // x-projections f32: [r,u,h,zp,zq]
__device__ float g_U  [4096 * 256];
__device__ float g_HD [4096 * 1024];            // [mu_p | lp | mu_q | lq]
__device__ float g_Hf [2 * 4096 * 256];         // f32 h state (prev/next)
__device__ float g_G  [131072 * 128];
// fp16 hi/lo slabs: [row][512] = [hi|lo]
__device__ __align__(16) __half g_Xs  [(size_t)131072 * 512];
__device__ __align__(16) __half g_Hseq[(size_t)131072 * 512];
__device__ __align__(16) __half g_Zseq[(size_t)131072 * 512];
__device__ __align__(16) __half g_Hst [2 * 4096 * 512];
__device__ __align__(16) __half g_Zst [2 * 4096 * 512];
__device__ __align__(16) __half g_RH  [4096 * 512];
__device__ __align__(16) __half g_HZP [4096 * 512];
__device__ __align__(16) __half g_HZQ [4096 * 512];
// prepacked weights: fp16 hi only, transposed, [N][K] K-major
constexpr size_t O1 = 0;                  // [1280][256]
constexpr size_t O2 = O1 + 1280 * 256;    // [512][512]
constexpr size_t O3 = O2 + 512 * 512;     // [256][512]
constexpr size_t O4 = O3 + 256 * 512;     // [512][256]
constexpr size_t O5 = O4 + 512 * 256;     // [1024][256]
constexpr size_t O6 = O5 + 1024 * 256;    // [128][768]
constexpr size_t WTOT = O6 + 128 * 768;
__device__ __align__(16) __half g_Wp[WTOT];

// ============================ A descriptor ============================
struct ADesc { const __half* s0[3]; const __half* s1[3]; };

// ============================ Epilogues ============================
struct EP_AX {
    float* AX; const float* bias[5]; const float* yph; const float* WzqY;
    DI void operator()(int row, int col, float acc) const {
        int seg = col >> 8, c = col & 255;
        float v = acc + bias[seg][c];
        if (seg == 4)
            v += yph[(size_t)row * 2] * WzqY[c] + yph[(size_t)row * 2 + 1] * WzqY[256 + c];
        AX[(size_t)row * 1280 + col] = v;
    }
};
struct EP_RU { // r -> RH slab (r*h_prev), u -> f32 U
    const float* AX; const float* hpf; float* U; __half* RH; int t;
    DI void operator()(int b, int col, float acc) const {
        size_t bt = (size_t)b * Tn + t;
        float pre = acc + AX[bt * 1280 + col];
        if (col < 256) {
            float r = sigf(pre);
            slab_write(RH, b, col, r * hpf[b * 256 + col]);
        } else {
            U[b * 256 + col - 256] = sigf(pre);
        }
    }
};
struct EP_H {
    const float* AX; const float* U; const float* hpf; float* hnf;
    __half* Hst; __half* Hseq; int t;
    DI void operator()(int b, int c, float acc) const {
        size_t bt = (size_t)b * Tn + t;
        float ht = tanhf(acc + AX[bt * 1280 + 512 + c]);
        float u  = U[b * 256 + c];
        float h  = (1.0f - u) * hpf[b * 256 + c] + u * ht;
        hnf[b * 256 + c] = h;
        slab_write(Hst, b, c, h);
        slab_write(Hseq, bt, c, h);
    }
};
struct EP_ZPQ {
    const float* AX; __half* P; __half* Q; int t;
    DI void operator()(int b, int col, float acc) const {
        size_t bt = (size_t)b * Tn + t;
        if (col < 256) slab_write(P, b, col, tanhf(acc + AX[bt * 1280 + 768 + col]));
        else           slab_write(Q, b, col - 256, tanhf(acc + AX[bt * 1280 + 1024 + (col - 256)]));
    }
};
struct EP_HEADS {
    float* HD; const float* bias[4];
    DI void operator()(int b, int col, float acc) const {
        int seg = col >> 8, c = col & 255;
        HD[(size_t)b * 1024 + col] = acc + bias[seg][c];
    }
};
struct EP_G {
    float* G; const float* bg;
    DI void operator()(int row, int col, float acc) const {
        G[(size_t)row * 128 + col] = tanhf(acc + bg[col]);
    }
};

// ============================ fp16 2-term split mma.sync GEMM ============================
// CTA tile 64xBN (BN=128 or 64). BK=32 fp16 per chunk; K' = 2K (Ahi·Bhi + Alo·Bhi).
// BN=128: 8 warps 2(m)x4(n), warp 32x32. BN=64: 8 warps 4(m)x2(n), warp 16x32.
// SMEM: 6 stages x (A 64x80B + B BNx80B), cp.async pipeline, always-commit.
template <int BN, class EP>
__global__ __launch_bounds__(256, 2)
void tgemm(ADesc ad, EP ep, const __half* __restrict__ Bp, int K) {
    constexpr int WN_ = (BN == 128) ? 4 : 2;    // warps along N
    constexpr int WM_ = 8 / WN_;                // warps along M
    constexpr int WTM = 64 / WM_;               // warp tile M (32 or 16)
    constexpr int WTN = BN / WN_;               // warp tile N (32)
    constexpr int MF  = WTM / 16;               // m fragments
    constexpr int NF  = WTN / 8;                // n fragments
    constexpr int NB  = WTN / 16;               // B ldm_x4 count
    constexpr int A_T = 64 * 80;
    constexpr int B_T = BN * 80;
    constexpr int STG = A_T + B_T;
    constexpr int NSTG = 6;

    extern __shared__ __align__(16) uint8_t smem[];
    const uint32_t sb = smem_u32(smem);

    const int tid  = threadIdx.x;
    const int lane = tid & 31;
    const int warp = tid >> 5;
    const int m0 = blockIdx.y * 64;
    const int n0 = blockIdx.x * BN;
    const int nseg = n0 >> 8;
    const int warpM = (warp / WN_) * WTM;
    const int warpN = (warp % WN_) * WTN;
    const int cpt = K >> 5;       // 32-K chunks per split term
    const int nch = 2 * cpt;

    const __half* const* slabs = (nseg < 2) ? ad.s0 : ad.s1;

    float acc[MF][NF][4];
#pragma unroll
    for (int i = 0; i < MF; i++)
#pragma unroll
        for (int j = 0; j < NF; j++)
#pragma unroll
            for (int q = 0; q < 4; q++) acc[i][j][q] = 0.0f;

    auto fill = [&](int ch, int stg) {
        int term = ch >= cpt;
        int chk = term ? ch - cpt : ch;
        { // A: 64 rows x 64B = 256 x 16B chunks
            int row = tid >> 2, q = tid & 3;
            int kk = chk * 32 + q * 8;
            int slab = kk >> 8, o = kk & 255;
            const __half* src = slabs[slab] + (size_t)(m0 + row) * 512 + term * 256 + o;
            cp16(sb + stg * STG + row * 80 + q * 16, src);
        }
        // B: BN rows x 64B
#pragma unroll
        for (int c = 0; c < BN / 64; c++) {
            int id = c * 256 + tid;
            int row = id >> 2, q = id & 3;
            const __half* bs = Bp + (size_t)(n0 + row) * K + chk * 32 + q * 8;
            cp16(sb + stg * STG + A_T + row * 80 + q * 16, bs);
        }
    };

    auto mmastep = [&](int stg) {
        const uint32_t Ab = sb + stg * STG;
        const uint32_t Bb = Ab + A_T;
#pragma unroll
        for (int ks = 0; ks < 2; ks++) {
            uint32_t afr[MF][4];
#pragma unroll
            for (int mf = 0; mf < MF; mf++)
                ldm_x4(afr[mf], Ab + (warpM + mf * 16 + (lane & 15)) * 80
                                   + ((ks << 1) + (lane >> 4)) * 16);
            uint32_t bfr[NB][4];
#pragma unroll
            for (int j = 0; j < NB; j++)
                ldm_x4(bfr[j], Bb + (warpN + j * 16 + (lane & 7) + ((lane >> 4) & 1) * 8) * 80
                                  + ((ks << 1) + ((lane >> 3) & 1)) * 16);
#pragma unroll
            for (int mf = 0; mf < MF; mf++)
#pragma unroll
                for (int nf = 0; nf < NF; nf++)
                    mma_f16(acc[mf][nf], afr[mf], &bfr[nf >> 1][(nf & 1) * 2]);
        }
    };

    // prologue: NSTG-1 = 5 chunks in flight
#pragma unroll
    for (int ch = 0; ch < NSTG - 1; ch++) {
        if (ch < nch) fill(ch, ch);
        CP_COMMIT();
    }

    for (int i = 0; i < nch; i++) {
        CP_WAIT(NSTG - 2);
        __syncthreads();
        // refill stage (i+5)%6 == (i-1)%6 — safe: sync above guarantees all
        // warps finished mma on that stage last iteration
        if (i + NSTG - 1 < nch) fill(i + NSTG - 1, (i + NSTG - 1) % NSTG);
        CP_COMMIT();
        mmastep(i % NSTG);
    }

    // register-direct fused epilogue (mma.m16n8k16 C fragment mapping)
#pragma unroll
    for (int mf = 0; mf < MF; mf++)
#pragma unroll
        for (int nf = 0; nf < NF; nf++)
#pragma unroll
            for (int j = 0; j < 4; j++) {
                int m = m0 + warpM + mf * 16 + (lane >> 2) + ((j >> 1) << 3);
                int n = n0 + warpN + (nf >> 1) * 16 + (nf & 1) * 8 + ((lane & 3) << 1) + (j & 1);
                ep(m, n, acc[mf][nf][j]);
            }
}
constexpr int SMEM128 = 6 * (64 + 128) * 80;   // 92160
constexpr int SMEM64  = 6 * (64 + 64) * 80;    // 61440

// ============================ fused weight prep ============================
struct PrepSrc { const float* w[10]; }; // Wr,Wu,Wh,Wzp,Wzq,Wpm,Wps,Wqm,Wqs,Wg

__global__ void prep_all(PrepSrc ps, __half* __restrict__ dst) {
    struct S { int si, sld, sr0; size_t doff; int dr0, K, N; };
    const S tab[15] = {
        {0, 256,   0, O1,    0, 256, 256}, {1, 256,   0, O1,  256, 256, 256},
        {2, 256,   0, O1,  512, 256, 256}, {3, 256,   0, O1,  768, 256, 256},
        {4, 256,   0, O1, 1024, 256, 256},
        {0, 256, 256, O2,    0, 512, 256}, {1, 256, 256, O2,  256, 512, 256},
        {2, 256, 256, O3,    0, 512, 256},
        {3, 256, 256, O4,    0, 256, 256}, {4, 256, 256, O4,  256, 256, 256},
        {5, 256,   0, O5,    0, 256, 256}, {6, 256,   0, O5,  256, 256, 256},
        {7, 256,   0, O5,  512, 256, 256}, {8, 256,   0, O5,  768, 256, 256},
        {9, 128,   0, O6,    0, 768, 128},
    };
    const int cnt[15] = {65536,65536,65536,65536,65536, 131072,131072, 131072,
                         65536,65536, 65536,65536,65536,65536, 98304};
    int e = blockIdx.x * 256 + threadIdx.x;
    if (e >= 1212416) return;
    int s = 14;
    int base = 0;
#pragma unroll
    for (int i = 0; i < 15; i++) {
        int nb = base + cnt[i];
        if (e < nb) { s = i; break; }
        base = nb;
    }
    const S& t = tab[s];
    int local = e - base;
    int k = local / t.N, n = local % t.N;
    float v = ps.w[t.si][(size_t)(t.sr0 + k) * t.sld + n];
    dst[t.doff + (size_t)(t.dr0 + n) * t.K + k] = __float2half_rn(v);
}

// ============================ small kernels ============================
__global__ void init_copy(const float* __restrict__ x, const float* __restrict__ h0,
                          const float* __restrict__ z0, __half* __restrict__ Xs,
                          float* __restrict__ Hf, __half* __restrict__ Hst,
                          __half* __restrict__ Zst) {
    size_t idx = (size_t)blockIdx.x * blockDim.x + threadIdx.x;
    size_t r = idx >> 8;
    int k = (int)(idx & 255);
    slab_write(Xs, r, k, x[idx]);
    if (idx < (size_t)Bn * Hn) {
        float hv = h0[idx], zv = z0[idx];
        Hf[idx] = hv;
        slab_write(Hst, r, k, hv);
        slab_write(Zst, r, k, zv);
    }
}

__global__ void step_latent(const float* __restrict__ HD, const float* __restrict__ eps_t,
                            __half* __restrict__ Zst, __half* __restrict__ Zseq,
                            float* __restrict__ outKL, int t) {
    int b = blockIdx.x, c = threadIdx.x;
    size_t hb = (size_t)b * 1024;
    float mup = HD[hb + c];
    float lp  = HD[hb + 256 + c];
    float muq = HD[hb + 512 + c];
    float lq  = HD[hb + 768 + c];
    float z = muq + expf(0.5f * lq) * eps_t[b * 256 + c];
    size_t bt = (size_t)b * Tn + t;
    slab_write(Zst, b, c, z);
    slab_write(Zseq, bt, c, z);
    float d = muq - mup;
    float kl = 0.5f * (lp - lq) + (expf(lq) + d * d) / (2.0f * expf(lp)) - 0.5f;

    __shared__ float red[8];
    for (int o = 16; o; o >>= 1) kl += __shfl_down_sync(0xffffffffu, kl, o);
    if ((threadIdx.x & 31) == 0) red[threadIdx.x >> 5] = kl;
    __syncthreads();
    if (threadIdx.x == 0) {
        float s = 0.0f;
#pragma unroll
        for (int i = 0; i < 8; i++) s += red[i];
        outKL[bt] = s;
    }
}

__global__ void yhead(const float* __restrict__ G, const float* __restrict__ Wy,
                      const float* __restrict__ by, float* __restrict__ outY) {
    int r = blockIdx.x * 8 + (threadIdx.x >> 5);
    int lane = threadIdx.x & 31;
    float s0 = 0.0f, s1 = 0.0f;
    const float* g = G + (size_t)r * 128;
    for (int k = lane; k < 128; k += 32) {
        float gv = g[k];
        s0 += gv * Wy[k * 2];
        s1 += gv * Wy[k * 2 + 1];
    }
    for (int o = 16; o; o >>= 1) {
        s0 += __shfl_down_sync(0xffffffffu, s0, o);
        s1 += __shfl_down_sync(0xffffffffu, s1, o);
    }
    if (lane == 0) {
        float l0 = s0 + by[0], l1 = s1 + by[1];
        float m = fmaxf(l0, l1);
        float e0 = expf(l0 - m), e1 = expf(l1 - m);
        float inv = 1.0f / (e0 + e1);
        outY[(size_t)r * 2]     = e0 * inv;
        outY[(size_t)r * 2 + 1] = e1 * inv;
    }
}

__global__ void gatherGT(const float* __restrict__ G, const int* __restrict__ Tph,
                         float* __restrict__ outGT) {
    int b = blockIdx.x;
    int t = Tph[b] - 1;
    outGT[(size_t)b * Gn + threadIdx.x] = G[((size_t)b * Tn + t) * Gn + threadIdx.x];
}

// ============================ launch ============================
extern "C" void kernel_launch(void* const* d_in, const int* in_sizes, int n_in,
                              void* d_out, int out_size) {
    const float* x   = (const float*)d_in[0];
    const float* yph = (const float*)d_in[1];
    const int*   Tph = (const int*)  d_in[2];
    const float* h0  = (const float*)d_in[3];
    const float* z0  = (const float*)d_in[4];
    const float* eps = (const float*)d_in[5];
    const float* Wr  = (const float*)d_in[6];  const float* br  = (const float*)d_in[7];
    const float* Wu  = (const float*)d_in[8];  const float* bu  = (const float*)d_in[9];
    const float* Wh  = (const float*)d_in[10]; const float* bh  = (const float*)d_in[11];
    const float* Wzp = (const float*)d_in[12]; const float* bzp = (const float*)d_in[13];
    const float* Wpm = (const float*)d_in[14]; const float* bpm = (const float*)d_in[15];
    const float* Wps = (const float*)d_in[16]; const float* bps = (const float*)d_in[17];
    const float* Wzq = (const float*)d_in[18]; const float* bzq = (const float*)d_in[19];
    const float* Wqm = (const float*)d_in[20]; const float* bqm = (const float*)d_in[21];
    const float* Wqs = (const float*)d_in[22]; const float* bqs = (const float*)d_in[23];
    const float* Wg  = (const float*)d_in[24]; const float* bg  = (const float*)d_in[25];
    const float* Wy  = (const float*)d_in[26]; const float* by  = (const float*)d_in[27];

    float *AX, *U, *HD, *Hf, *Gb;
    __half *Xs, *Hseq, *Zseq, *Hst, *Zst, *RH, *HZP, *HZQ, *Wp;
    {
        void* p;
        cudaGetSymbolAddress(&p, g_AX);   AX   = (float*)p;
        cudaGetSymbolAddress(&p, g_U);    U    = (float*)p;
        cudaGetSymbolAddress(&p, g_HD);   HD   = (float*)p;
        cudaGetSymbolAddress(&p, g_Hf);   Hf   = (float*)p;
        cudaGetSymbolAddress(&p, g_G);    Gb   = (float*)p;
        cudaGetSymbolAddress(&p, g_Xs);   Xs   = (__half*)p;
        cudaGetSymbolAddress(&p, g_Hseq); Hseq = (__half*)p;
        cudaGetSymbolAddress(&p, g_Zseq); Zseq = (__half*)p;
        cudaGetSymbolAddress(&p, g_Hst);  Hst  = (__half*)p;
        cudaGetSymbolAddress(&p, g_Zst);  Zst  = (__half*)p;
        cudaGetSymbolAddress(&p, g_RH);   RH   = (__half*)p;
        cudaGetSymbolAddress(&p, g_HZP);  HZP  = (__half*)p;
        cudaGetSymbolAddress(&p, g_HZQ);  HZQ  = (__half*)p;
        cudaGetSymbolAddress(&p, g_Wp);   Wp   = (__half*)p;
    }

    cudaFuncSetAttribute((const void*)tgemm<128, EP_AX>,    cudaFuncAttributeMaxDynamicSharedMemorySize, SMEM128);
    cudaFuncSetAttribute((const void*)tgemm<128, EP_RU>,    cudaFuncAttributeMaxDynamicSharedMemorySize, SMEM128);
    cudaFuncSetAttribute((const void*)tgemm<64,  EP_H>,     cudaFuncAttributeMaxDynamicSharedMemorySize, SMEM64);
    cudaFuncSetAttribute((const void*)tgemm<128, EP_ZPQ>,   cudaFuncAttributeMaxDynamicSharedMemorySize, SMEM128);
    cudaFuncSetAttribute((const void*)tgemm<128, EP_HEADS>, cudaFuncAttributeMaxDynamicSharedMemorySize, SMEM128);
    cudaFuncSetAttribute((const void*)tgemm<128, EP_G>,     cudaFuncAttributeMaxDynamicSharedMemorySize, SMEM128);

    float* out   = (float*)d_out;
    float* outY  = out;
    float* outKL = out + (size_t)BT * Yn;
    float* outGT = out + (size_t)BT * Yn + BT;

    // ---- single fused weight prep ----
    {
        PrepSrc ps;
        ps.w[0] = Wr; ps.w[1] = Wu; ps.w[2] = Wh; ps.w[3] = Wzp; ps.w[4] = Wzq;
        ps.w[5] = Wpm; ps.w[6] = Wps; ps.w[7] = Wqm; ps.w[8] = Wqs; ps.w[9] = Wg;
        prep_all<<<(1212416 + 255) / 256, 256>>>(ps, Wp);
    }

    init_copy<<<BT, 256>>>(x, h0, z0, Xs, Hf, Hst, Zst);

    dim3 blk(256);

    // phase 1: x-projections  -> N=1280, K=256
    {
        ADesc ad{}; ad.s0[0] = Xs; ad.s1[0] = Xs;
        EP_AX ep;
        ep.AX = AX;
        ep.bias[0] = br; ep.bias[1] = bu; ep.bias[2] = bh; ep.bias[3] = bzp; ep.bias[4] = bzq;
        ep.yph = yph; ep.WzqY = Wzq + 512 * 256;
        tgemm<128><<<dim3(1280 / 128, BT / 64), blk, SMEM128>>>(ad, ep, Wp + O1, 256);
    }

    // phase 2: sequential scan
    for (int t = 0; t < Tn; t++) {
        int cur = t & 1, nxt = cur ^ 1;
        const float* hpf = Hf + (size_t)cur * Bn * Hn;
        float* hnf       = Hf + (size_t)nxt * Bn * Hn;
        __half* HstC = Hst + (size_t)cur * Bn * 512;
        __half* HstN = Hst + (size_t)nxt * Bn * 512;
        __half* ZstC = Zst + (size_t)cur * Bn * 512;
        __half* ZstN = Zst + (size_t)nxt * Bn * 512;

        { // gates r,u: A = [h_prev | z_prev], N=512, K=512 -> 256 CTAs
            ADesc ad{}; ad.s0[0] = HstC; ad.s0[1] = ZstC; ad.s1[0] = HstC; ad.s1[1] = ZstC;
            EP_RU ep{AX, hpf, U, RH, t};
            tgemm<128><<<dim3(512 / 128, Bn / 64), blk, SMEM128>>>(ad, ep, Wp + O2, 512);
        }
        { // candidate + GRU update: A = [r*h_prev | z_prev], N=256, K=512 -> 256 CTAs
            ADesc ad{}; ad.s0[0] = RH; ad.s0[1] = ZstC; ad.s1[0] = RH; ad.s1[1] = ZstC;
            EP_H ep{AX, U, hpf, hnf, HstN, Hseq, t};
            tgemm<64><<<dim3(256 / 64, Bn / 64), blk, SMEM64>>>(ad, ep, Wp + O3, 512);
        }
        { // latent hiddens: A = h_new, N=512, K=256 -> 256 CTAs
            ADesc ad{}; ad.s0[0] = HstN; ad.s1[0] = HstN;
            EP_ZPQ ep{AX, HZP, HZQ, t};
            tgemm<128><<<dim3(512 / 128, Bn / 64), blk, SMEM128>>>(ad, ep, Wp + O4, 256);
        }
        { // heads: N=1024, K=256 -> 512 CTAs; A = HZP segs 0-1, HZQ segs 2-3
            ADesc ad{}; ad.s0[0] = HZP; ad.s1[0] = HZQ;
            EP_HEADS ep;
            ep.HD = HD;
            ep.bias[0] = bpm; ep.bias[1] = bps; ep.bias[2] = bqm; ep.bias[3] = bqs;
            tgemm<128><<<dim3(1024 / 128, Bn / 64), blk, SMEM128>>>(ad, ep, Wp + O5, 256);
        }
        step_latent<<<Bn, 256>>>(HD, eps + (size_t)t * Bn * Zn, ZstN, Zseq, outKL, t);
    }

    // phase 3: g = tanh([x|h|z] @ Wg + bg), N=128, K=768
    {
        ADesc ad{}; ad.s0[0] = Xs; ad.s0[1] = Hseq; ad.s0[2] = Zseq;
        ad.s1[0] = Xs; ad.s1[1] = Hseq; ad.s1[2] = Zseq;
        EP_G ep{Gb, bg};
        tgemm<128><<<dim3(Gn / 128, BT / 64), blk, SMEM128>>>(ad, ep, Wp + O6, 768);
    }
    yhead<<<BT / 8, 256>>>(Gb, Wy, by, outY);
    gatherGT<<<Bn, Gn>>>(Gb, Tph, outGT);
}